// round 1
// baseline (speedup 1.0000x reference)
#include <cuda_runtime.h>

typedef unsigned int u32;
typedef unsigned long long u64;

// ---- packed f32x2 helpers (Blackwell sm_103a) ------------------------------
__device__ __forceinline__ u64 pack2(float lo, float hi) {
    u64 r; asm("mov.b64 %0, {%1, %2};" : "=l"(r) : "f"(lo), "f"(hi)); return r;
}
__device__ __forceinline__ void unpack2(u64 v, float& lo, float& hi) {
    asm("mov.b64 {%0, %1}, %2;" : "=f"(lo), "=f"(hi) : "l"(v));
}
__device__ __forceinline__ void fma2(u64& d, u64 a, u64 b, u64 c) {
    asm("fma.rn.f32x2 %0, %1, %2, %3;" : "=l"(d) : "l"(a), "l"(b), "l"(c));
}

#define H2C 2654435761u
#define H3C 805459861u

__global__ void __launch_bounds__(128) nerf_fused(
    const float* __restrict__ xin,     // (N,19)
    const float* __restrict__ grids,   // (16, 524288, 2)
    const float* __restrict__ gw_s1,   // (32,64)
    const float* __restrict__ gw_s2,   // (64,16)
    const float* __restrict__ gw_c1,   // (32,64)
    const float* __restrict__ gw_c2,   // (64,64)
    const float* __restrict__ gw_c3,   // (64,3)
    float* __restrict__ out,           // (N,4)
    int N)
{
    __shared__ __align__(16) float s1[32*64];
    __shared__ __align__(16) float s2[64*16];
    __shared__ __align__(16) float c1w[32*64];
    __shared__ __align__(16) float c2w[64*64];
    __shared__ __align__(16) float c3w[64*3];

    const int tid = threadIdx.x;
    for (int t = tid; t < 2048; t += 128) s1[t]  = gw_s1[t];
    for (int t = tid; t < 1024; t += 128) s2[t]  = gw_s2[t];
    for (int t = tid; t < 2048; t += 128) c1w[t] = gw_c1[t];
    for (int t = tid; t < 4096; t += 128) c2w[t] = gw_c2[t];
    for (int t = tid; t < 192;  t += 128) c3w[t] = gw_c3[t];
    __syncthreads();

    const int i = blockIdx.x * 128 + tid;
    if (i >= N) return;

    const float px = xin[(size_t)i*19 + 0];
    const float py = xin[(size_t)i*19 + 1];
    const float pz = xin[(size_t)i*19 + 2];

    // levels: PER_LEVEL_SCALE = float32(2^0.4) (rounded up) =>
    // res = ceil(16*s^l) with s^5 = 4*(1+1.73e-7) etc. => 65/257/1025 at l=5/10/15.
    const int RES_[16]  = {16,22,28,37,49,65,85,112,148,195,257,338,446,589,777,1025};
    const u32 SZ_[16]   = {4096u,10648u,21952u,50656u,117656u,274632u,
                           524288u,524288u,524288u,524288u,524288u,
                           524288u,524288u,524288u,524288u,524288u};
    // MAX_DIRECT = 2 (37^3, 49^3, 65^3 are odd -> padded -> not "direct")

    // gemm1 accumulators (enc @ w_sigma1), fused into the gather loop.
    u64 acc[32];
    #pragma unroll
    for (int j = 0; j < 32; j++) acc[j] = 0ull;

    const ulonglong2* W1 = (const ulonglong2*)s1;

    #pragma unroll
    for (int l = 0; l < 16; l++) {
        const int R = RES_[l];
        const u32 S = SZ_[l];
        const float Rf = (float)R;
        float u = px * Rf, v = py * Rf, w = pz * Rf;
        float fu = floorf(u), fv = floorf(v), fw = floorf(w);
        float fx = u - fu, fy = v - fv, fz = w - fw;
        int ix = (int)fu, iy = (int)fv, iz = (int)fw;

        u32 idx[8];
        if (l <= 2) {
            #pragma unroll
            for (int j = 0; j < 8; j++) {
                int cx = ix + ((j >> 2) & 1);
                int cy = iy + ((j >> 1) & 1);
                int cz = iz + (j & 1);
                idx[j] = (u32)(cz * (R * R) + cy * R + cx) % S;
            }
        } else {
            u32 hx0 = (u32)ix;           u32 hx1 = hx0 + 1u;
            u32 hy0 = (u32)iy * H2C;     u32 hy1 = hy0 + H2C;
            u32 hz0 = (u32)iz * H3C;     u32 hz1 = hz0 + H3C;
            #pragma unroll
            for (int j = 0; j < 8; j++) {
                u32 h = ((j & 4) ? hx1 : hx0) ^ ((j & 2) ? hy1 : hy0) ^ ((j & 1) ? hz1 : hz0);
                idx[j] = (l >= 6) ? (h & 524287u) : (h % S);
            }
        }

        const float2* g = (const float2*)grids + (size_t)l * 524288u;
        float2 cc[8];
        #pragma unroll
        for (int j = 0; j < 8; j++) cc[j] = __ldg(g + idx[j]);

        const float gx = 1.f - fx, gy = 1.f - fy, gz = 1.f - fz;
        float c00x = cc[0].x*gx + cc[4].x*fx, c00y = cc[0].y*gx + cc[4].y*fx;
        float c01x = cc[1].x*gx + cc[5].x*fx, c01y = cc[1].y*gx + cc[5].y*fx;
        float c10x = cc[2].x*gx + cc[6].x*fx, c10y = cc[2].y*gx + cc[6].y*fx;
        float c11x = cc[3].x*gx + cc[7].x*fx, c11y = cc[3].y*gx + cc[7].y*fx;
        float c0x = c00x*gy + c10x*fy, c0y = c00y*gy + c10y*fy;
        float c1x = c01x*gy + c11x*fy, c1y = c01y*gy + c11y*fy;
        // NOTE: replicates reference bug: c0*(1-fz) + c1*fy   (fy, not fz!)
        float fex = c0x*gz + c1x*fy;
        float fey = c0y*gz + c1y*fy;

        // gemm1 partial: k = 2l and 2l+1
        u64 a0 = pack2(fex, fex);
        u64 a1 = pack2(fey, fey);
        #pragma unroll
        for (int j = 0; j < 16; j++) {
            ulonglong2 w0 = W1[(2*l)     * 16 + j];
            ulonglong2 w1 = W1[(2*l + 1) * 16 + j];
            fma2(acc[2*j],   a0, w0.x, acc[2*j]);
            fma2(acc[2*j+1], a0, w0.y, acc[2*j+1]);
            fma2(acc[2*j],   a1, w1.x, acc[2*j]);
            fma2(acc[2*j+1], a1, w1.y, acc[2*j+1]);
        }
    }

    // relu -> h1[64]
    float h1[64];
    #pragma unroll
    for (int j = 0; j < 32; j++) {
        float lo, hi; unpack2(acc[j], lo, hi);
        h1[2*j]   = fmaxf(lo, 0.f);
        h1[2*j+1] = fmaxf(hi, 0.f);
    }

    // gemm2: out16 = h1 @ w_sigma2  (64x16)
    u64 o2[8];
    #pragma unroll
    for (int j = 0; j < 8; j++) o2[j] = 0ull;
    const ulonglong2* W2 = (const ulonglong2*)s2;
    #pragma unroll
    for (int k = 0; k < 64; k++) {
        u64 a = pack2(h1[k], h1[k]);
        #pragma unroll
        for (int j = 0; j < 4; j++) {
            ulonglong2 ww = W2[k*4 + j];
            fma2(o2[2*j],   a, ww.x, o2[2*j]);
            fma2(o2[2*j+1], a, ww.y, o2[2*j+1]);
        }
    }
    float ov[16];
    #pragma unroll
    for (int j = 0; j < 8; j++) unpack2(o2[j], ov[2*j], ov[2*j+1]);
    const float sigma = ov[0];

    // ci = [direc(16), ov(16)]
    float ci[32];
    #pragma unroll
    for (int t = 0; t < 16; t++) ci[t] = xin[(size_t)i*19 + 3 + t];
    #pragma unroll
    for (int t = 0; t < 16; t++) ci[16 + t] = ov[t];

    // gemm3: hc = relu(ci @ w_c1)  (32x64)
    u64 a3[32];
    #pragma unroll
    for (int j = 0; j < 32; j++) a3[j] = 0ull;
    const ulonglong2* Wc1 = (const ulonglong2*)c1w;
    #pragma unroll
    for (int k = 0; k < 32; k++) {
        u64 a = pack2(ci[k], ci[k]);
        #pragma unroll
        for (int j = 0; j < 16; j++) {
            ulonglong2 ww = Wc1[k*16 + j];
            fma2(a3[2*j],   a, ww.x, a3[2*j]);
            fma2(a3[2*j+1], a, ww.y, a3[2*j+1]);
        }
    }
    float hc[64];
    #pragma unroll
    for (int j = 0; j < 32; j++) {
        float lo, hi; unpack2(a3[j], lo, hi);
        hc[2*j]   = fmaxf(lo, 0.f);
        hc[2*j+1] = fmaxf(hi, 0.f);
    }

    // gemm4 (64x64) split into two 32-wide halves + gemm5 (64x3) fused,
    // to cap register pressure.
    float col0 = 0.f, col1 = 0.f, col2 = 0.f;
    const ulonglong2* Wc2 = (const ulonglong2*)c2w;
    #pragma unroll
    for (int half = 0; half < 2; half++) {
        u64 a4[16];
        #pragma unroll
        for (int j = 0; j < 16; j++) a4[j] = 0ull;
        #pragma unroll
        for (int k = 0; k < 64; k++) {
            u64 a = pack2(hc[k], hc[k]);
            #pragma unroll
            for (int j = 0; j < 8; j++) {
                ulonglong2 ww = Wc2[k*16 + half*8 + j];
                fma2(a4[2*j],   a, ww.x, a4[2*j]);
                fma2(a4[2*j+1], a, ww.y, a4[2*j+1]);
            }
        }
        // relu + w_c3 contribution of this half
        #pragma unroll
        for (int q = 0; q < 16; q++) {
            float lo, hi; unpack2(a4[q], lo, hi);
            lo = fmaxf(lo, 0.f); hi = fmaxf(hi, 0.f);
            int m = half*32 + 2*q;
            col0 += lo * c3w[m*3 + 0] + hi * c3w[(m+1)*3 + 0];
            col1 += lo * c3w[m*3 + 1] + hi * c3w[(m+1)*3 + 1];
            col2 += lo * c3w[m*3 + 2] + hi * c3w[(m+1)*3 + 2];
        }
    }

    // sigmoid
    col0 = 1.f / (1.f + expf(-col0));
    col1 = 1.f / (1.f + expf(-col1));
    col2 = 1.f / (1.f + expf(-col2));

    float4 r; r.x = col0; r.y = col1; r.z = col2; r.w = sigma;
    ((float4*)out)[i] = r;
}

extern "C" void kernel_launch(void* const* d_in, const int* in_sizes, int n_in,
                              void* d_out, int out_size) {
    const float* x     = (const float*)d_in[0];
    const float* grids = (const float*)d_in[1];
    const float* ws1   = (const float*)d_in[2];
    const float* ws2   = (const float*)d_in[3];
    const float* wc1   = (const float*)d_in[4];
    const float* wc2   = (const float*)d_in[5];
    const float* wc3   = (const float*)d_in[6];
    float* out = (float*)d_out;

    const int N = in_sizes[0] / 19;
    const int blocks = (N + 127) / 128;
    nerf_fused<<<blocks, 128>>>(x, grids, ws1, ws2, wc1, wc2, wc3, out, N);
}